// round 11
// baseline (speedup 1.0000x reference)
#include <cuda_runtime.h>
#include <cuda_fp16.h>
#include <cstdint>

#define DINLINE __device__ __forceinline__

static constexpr int B_ROWS = 4096;
static constexpr int D_DIM  = 256;
static constexpr int N_TOT  = 8192;
static constexpr int TILE   = 128;
static constexpr int NTRI   = 2080;          // upper-triangle tiles
static constexpr int NCTA   = 148;

static constexpr float EXP_K = 2.8853900817779268f;  // 2/ln(2)

// ---- device scratch ----
__device__ __align__(16) __half g_Z[N_TOT * D_DIM];
__device__ float g_denom[N_TOT];

// ============ helpers ============
DINLINE uint32_t smem_u32(const void* p) {
    uint32_t a;
    asm("{ .reg .u64 t; cvta.to.shared.u64 t, %1; cvt.u32.u64 %0, t; }" : "=r"(a) : "l"(p));
    return a;
}
DINLINE void ldsm_x4(uint32_t addr, uint32_t* r) {
    asm volatile("ldmatrix.sync.aligned.m8n8.x4.shared.b16 {%0,%1,%2,%3}, [%4];"
                 : "=r"(r[0]), "=r"(r[1]), "=r"(r[2]), "=r"(r[3]) : "r"(addr));
}
DINLINE void mma16816(float4& c, const uint32_t* a, uint32_t b0, uint32_t b1) {
    asm volatile(
        "mma.sync.aligned.m16n8k16.row.col.f32.f16.f16.f32 "
        "{%0,%1,%2,%3}, {%4,%5,%6,%7}, {%8,%9}, {%0,%1,%2,%3};"
        : "+f"(c.x), "+f"(c.y), "+f"(c.z), "+f"(c.w)
        : "r"(a[0]), "r"(a[1]), "r"(a[2]), "r"(a[3]), "r"(b0), "r"(b1));
}
DINLINE float ex2f(float x) {
    float e;
    asm("ex2.approx.f32 %0, %1;" : "=f"(e) : "f"(x));
    return e;
}

// ============ SMEM layout ============
static constexpr int ROW_BYTES  = 528;               // 256 fp16 + 16B pad
static constexpr int TILE_BYTES = 128 * ROW_BYTES;   // 67584
static constexpr int SMEM_A     = 1024;
static constexpr int SMEM_B0    = SMEM_A + TILE_BYTES;    // 68608
static constexpr int SMEM_B1    = SMEM_B0 + TILE_BYTES;   // 136192
static constexpr int SMEM_TOTAL = SMEM_B1 + TILE_BYTES;   // 203776

DINLINE void load_tile(uint32_t smem_dst, const __half* gsrc, int tid) {
#pragma unroll
    for (int i = 0; i < 16; ++i) {
        int u = tid + i * 256;
        int r = u >> 5, c = u & 31;
        uint32_t saddr = smem_dst + (uint32_t)r * ROW_BYTES + (uint32_t)c * 16;
        const char* g = (const char*)gsrc + (size_t)u * 16;
        asm volatile("cp.async.cg.shared.global [%0], [%1], 16;" :: "r"(saddr), "l"(g));
    }
}

// ============ kernel 1: normalize (row per warp) + zero denom/out ============
__global__ void __launch_bounds__(256) k_normalize(const float* __restrict__ q,
                                                   const float* __restrict__ p,
                                                   float* __restrict__ out) {
    const int wid  = threadIdx.x >> 5;
    const int lane = threadIdx.x & 31;
    const int row  = blockIdx.x * 8 + wid;
    if (threadIdx.x < 8) g_denom[blockIdx.x * 8 + threadIdx.x] = 0.0f;
    if (blockIdx.x == 0 && threadIdx.x == 0) out[0] = 0.0f;

    const float* src = (row < B_ROWS) ? q + (size_t)row * D_DIM
                                      : p + (size_t)(row - B_ROWS) * D_DIM;
    float4 v0 = ((const float4*)src)[lane * 2];
    float4 v1 = ((const float4*)src)[lane * 2 + 1];
    float ss = v0.x * v0.x + v0.y * v0.y + v0.z * v0.z + v0.w * v0.w
             + v1.x * v1.x + v1.y * v1.y + v1.z * v1.z + v1.w * v1.w;
#pragma unroll
    for (int o = 16; o; o >>= 1) ss += __shfl_xor_sync(0xffffffffu, ss, o);
    float inv = 1.0f / fmaxf(sqrtf(ss), 1e-12f);

    __half2 h[4];
    h[0] = __floats2half2_rn(v0.x * inv, v0.y * inv);
    h[1] = __floats2half2_rn(v0.z * inv, v0.w * inv);
    h[2] = __floats2half2_rn(v1.x * inv, v1.y * inv);
    h[3] = __floats2half2_rn(v1.z * inv, v1.w * inv);
    ((uint4*)(g_Z + (size_t)row * D_DIM))[lane] = *(const uint4*)h;
}

// ============ gemm building blocks ============
// One 32-col half of a warp's 32x64 tile: 16 k-steps of (2 B-ldsm + 8 MMA),
// with the epilogue of the PREVIOUS half interleaved (DO_EPI).
template<bool DO_EPI>
DINLINE void phase_mma(uint32_t bb, const uint32_t areg[16][8],
                       float4 accN[8], const float4 accP[8],
                       float colP[8], float rsum[2][2]) {
#pragma unroll
    for (int i = 0; i < 8; ++i) accN[i] = make_float4(0.f, 0.f, 0.f, 0.f);
#pragma unroll
    for (int ks = 0; ks < 16; ++ks) {
        uint32_t b0[4], b1[4];
        ldsm_x4(bb + (uint32_t)ks * 32, b0);
        ldsm_x4(bb + 16u * ROW_BYTES + (uint32_t)ks * 32, b1);
        mma16816(accN[0], areg[ks],     b0[0], b0[2]);
        mma16816(accN[1], areg[ks],     b0[1], b0[3]);
        mma16816(accN[2], areg[ks],     b1[0], b1[2]);
        mma16816(accN[3], areg[ks],     b1[1], b1[3]);
        mma16816(accN[4], areg[ks] + 4, b0[0], b0[2]);
        mma16816(accN[5], areg[ks] + 4, b0[1], b0[3]);
        mma16816(accN[6], areg[ks] + 4, b1[0], b1[2]);
        mma16816(accN[7], areg[ks] + 4, b1[1], b1[3]);
        if (DO_EPI && ((ks & 1) == 0)) {
            const int e  = ks >> 1;            // 0..7
            const int mi = e >> 2, g = e & 3;
            float4 c = accP[e];
            float ex = ex2f(c.x * EXP_K), ey = ex2f(c.y * EXP_K);
            float ez = ex2f(c.z * EXP_K), ew = ex2f(c.w * EXP_K);
            rsum[mi][0] += ex + ey;
            rsum[mi][1] += ez + ew;
            colP[g * 2]     += ex + ez;
            colP[g * 2 + 1] += ey + ew;
        }
    }
}

// Exposed epilogue (used once per strip-run to flush the pipeline)
DINLINE void flush_acc(const float4 accP[8], float colP[8], float rsum[2][2]) {
#pragma unroll
    for (int e = 0; e < 8; ++e) {
        const int mi = e >> 2, g = e & 3;
        float4 c = accP[e];
        float ex = ex2f(c.x * EXP_K), ey = ex2f(c.y * EXP_K);
        float ez = ex2f(c.z * EXP_K), ew = ex2f(c.w * EXP_K);
        rsum[mi][0] += ex + ey;
        rsum[mi][1] += ez + ew;
        colP[g * 2]     += ex + ez;
        colP[g * 2 + 1] += ey + ew;
    }
}

// Reduce a half's column partials across the warp and REDG them to g_denom.
DINLINE void finish_cols(float colP[8], int colbase, bool offdiag, int lane) {
#pragma unroll
    for (int i = 0; i < 8; ++i) {
        float v = colP[i];
        v += __shfl_xor_sync(0xffffffffu, v, 4);
        v += __shfl_xor_sync(0xffffffffu, v, 8);
        v += __shfl_xor_sync(0xffffffffu, v, 16);
        colP[i] = v;
    }
    if (offdiag && lane < 4) {
#pragma unroll
        for (int g = 0; g < 4; ++g) {
            atomicAdd(&g_denom[colbase + g * 8 + lane * 2],     colP[g * 2]);
            atomicAdd(&g_denom[colbase + g * 8 + lane * 2 + 1], colP[g * 2 + 1]);
        }
    }
#pragma unroll
    for (int i = 0; i < 8; ++i) colP[i] = 0.f;
}

// ============ kernel 2: pipelined upper-triangle Gram ============
// 148 CTAs, 8 warps as 4(M) x 2(N); warp tile 32x64 split in two 32-col halves.
// Epilogue of half h-1 overlaps MMA of half h (cross-tile pipeline).
__global__ void __launch_bounds__(256, 1) k_gemm_denom() {
    extern __shared__ __align__(1024) char smem[];
    const int tid    = threadIdx.x;
    const int wid    = tid >> 5;
    const int lane   = tid & 31;
    const int warp_m = wid & 3;
    const int warp_n = wid >> 2;
    uint32_t sbase = smem_u32(smem);

    const uint32_t lrow  = (uint32_t)(lane & 15) * ROW_BYTES + (uint32_t)(lane >> 4) * 16;
    const uint32_t abase = sbase + SMEM_A + (uint32_t)(warp_m * 32) * ROW_BYTES + lrow;
    const uint32_t boff  = (uint32_t)(warp_n * 64) * ROW_BYTES + lrow;

    const int t0 = (int)((unsigned)blockIdx.x * NTRI / NCTA);
    const int t1 = (int)(((unsigned)blockIdx.x + 1) * NTRI / NCTA);

    int t = t0;
#pragma unroll 1
    while (t < t1) {
        const int P = t / 65;
        const int r = t - P * 65;
        int it, jt0, runend;
        if (r < 64 - P) { it = P;      jt0 = P + r;                   runend = t + (64 - P - r); }
        else            { it = 63 - P; jt0 = (63 - P) + r - (64 - P); runend = t + (65 - r); }
        const int n = min(t1, runend) - t;

        load_tile(sbase + SMEM_A,  g_Z + (size_t)it * TILE * D_DIM, tid);
        load_tile(sbase + SMEM_B0, g_Z + (size_t)jt0 * TILE * D_DIM, tid);
        asm volatile("cp.async.commit_group;" ::: "memory");
        asm volatile("cp.async.wait_group 0;" ::: "memory");
        __syncthreads();

        // hoist A fragments for the whole strip into registers
        uint32_t areg[16][8];
#pragma unroll
        for (int ks = 0; ks < 16; ++ks) {
            ldsm_x4(abase + (uint32_t)ks * 32, areg[ks]);
            ldsm_x4(abase + 16u * ROW_BYTES + (uint32_t)ks * 32, areg[ks] + 4);
        }

        float4 accA[8], accB[8];
        float colA[8], colB[8];
#pragma unroll
        for (int i = 0; i < 8; ++i) { colA[i] = 0.f; colB[i] = 0.f; }
        float rsum[2][2] = {{0.f, 0.f}, {0.f, 0.f}};
        int  prev_jt  = jt0;
        bool prev_off = false;

#pragma unroll 1
        for (int idx = 0; idx < n; ++idx) {
            const int jt = jt0 + idx;
            if (idx > 0) {
                asm volatile("cp.async.wait_group 0;" ::: "memory");
                __syncthreads();   // B[idx] visible; prev buffers fully consumed
            }
            if (idx + 1 < n) {
                load_tile(sbase + ((idx + 1) & 1 ? SMEM_B1 : SMEM_B0),
                          g_Z + (size_t)(jt + 1) * TILE * D_DIM, tid);
                asm volatile("cp.async.commit_group;" ::: "memory");
            }
            const uint32_t bb  = sbase + ((idx & 1) ? SMEM_B1 : SMEM_B0) + boff;
            const bool     off = (jt != it);

            // half 0: MMA -> accA, epilogue of pending (prev tile's h1 in accB)
            if (idx == 0) {
                phase_mma<false>(bb, areg, accA, accB, colB, rsum);
            } else {
                phase_mma<true>(bb, areg, accA, accB, colB, rsum);
                finish_cols(colB, prev_jt * TILE + warp_n * 64 + 32, prev_off, lane);
            }
            // half 1: MMA -> accB, epilogue of this tile's h0 (accA)
            phase_mma<true>(bb + 32u * ROW_BYTES, areg, accB, accA, colA, rsum);
            finish_cols(colA, jt * TILE + warp_n * 64, off, lane);

            prev_jt = jt;
            prev_off = off;
        }

        // flush pending h1 of last tile
        flush_acc(accB, colB, rsum);
        finish_cols(colB, prev_jt * TILE + warp_n * 64 + 32, prev_off, lane);

        // strip row sums: intra-warp reduce + direct REDG
#pragma unroll
        for (int mi = 0; mi < 2; ++mi)
#pragma unroll
            for (int h = 0; h < 2; ++h) {
                float v = rsum[mi][h];
                v += __shfl_xor_sync(0xffffffffu, v, 1);
                v += __shfl_xor_sync(0xffffffffu, v, 2);
                if ((lane & 3) == 0)
                    atomicAdd(&g_denom[it * TILE + warp_m * 32 + mi * 16 + h * 8 + (lane >> 2)], v);
            }
        __syncthreads();   // protect SMEM_A before next run overwrites it

        t += n;
    }
}

// ============ kernel 3: one pair per warp; positives + self-term removal + final sum ============
__global__ void __launch_bounds__(256) k_loss_partial(float* __restrict__ out) {
    const int wid  = threadIdx.x >> 5;
    const int lane = threadIdx.x & 31;
    const int i    = blockIdx.x * 8 + wid;         // pair 0..4095 (grid 512)

    uint4 a = ((const uint4*)(g_Z + (size_t)i * D_DIM))[lane];
    uint4 b = ((const uint4*)(g_Z + (size_t)(i + B_ROWS) * D_DIM))[lane];
    const __half2* pa = (const __half2*)&a;
    const __half2* pb = (const __half2*)&b;
    float d = 0.f, saa = 0.f, sbb = 0.f;
#pragma unroll
    for (int j = 0; j < 4; ++j) {
        float2 fa = __half22float2(pa[j]);
        float2 fb = __half22float2(pb[j]);
        d   += fa.x * fb.x + fa.y * fb.y;
        saa += fa.x * fa.x + fa.y * fa.y;
        sbb += fb.x * fb.x + fb.y * fb.y;
    }
#pragma unroll
    for (int o = 16; o; o >>= 1) {
        d   += __shfl_xor_sync(0xffffffffu, d, o);
        saa += __shfl_xor_sync(0xffffffffu, saa, o);
        sbb += __shfl_xor_sync(0xffffffffu, sbb, o);
    }
    __shared__ float sacc[8];
    if (lane == 0) {
        float di = g_denom[i]          - exp2f(saa * EXP_K);
        float dj = g_denom[i + B_ROWS] - exp2f(sbb * EXP_K);
        sacc[wid] = -4.0f * d + logf(di) + logf(dj);
    }
    __syncthreads();
    if (threadIdx.x == 0) {
        float s = 0.0f;
#pragma unroll
        for (int w = 0; w < 8; ++w) s += sacc[w];
        atomicAdd(out, s * (1.0f / (float)N_TOT));
    }
}

// ============ launch ============
extern "C" void kernel_launch(void* const* d_in, const int* in_sizes, int n_in,
                              void* d_out, int out_size) {
    const float* q = (const float*)d_in[0];
    const float* p = (const float*)d_in[1];
    (void)in_sizes; (void)n_in; (void)out_size;

    static bool attr_set = false;
    if (!attr_set) {
        cudaFuncSetAttribute(k_gemm_denom, cudaFuncAttributeMaxDynamicSharedMemorySize, SMEM_TOTAL);
        attr_set = true;
    }

    k_normalize<<<N_TOT / 8, 256>>>(q, p, (float*)d_out);
    k_gemm_denom<<<NCTA, 256, SMEM_TOTAL>>>();
    k_loss_partial<<<512, 256>>>((float*)d_out);
}

// round 12
// speedup vs baseline: 1.0036x; 1.0036x over previous
#include <cuda_runtime.h>
#include <cuda_fp16.h>
#include <cstdint>

#define DINLINE __device__ __forceinline__

static constexpr int B_ROWS = 4096;
static constexpr int D_DIM  = 256;
static constexpr int N_TOT  = 8192;
static constexpr int TILE   = 128;
static constexpr int NTRI   = 2080;          // upper-triangle tiles
static constexpr int NCTA   = 148;

static constexpr float EXP_K = 2.8853900817779268f;  // 2/ln(2)

// ---- device scratch ----
__device__ __align__(16) __half g_Z[N_TOT * D_DIM];
__device__ float g_denom[N_TOT];

// ============ helpers ============
DINLINE uint32_t smem_u32(const void* p) {
    uint32_t a;
    asm("{ .reg .u64 t; cvta.to.shared.u64 t, %1; cvt.u32.u64 %0, t; }" : "=r"(a) : "l"(p));
    return a;
}
DINLINE void ldsm_x4(uint32_t addr, uint32_t* r) {
    asm volatile("ldmatrix.sync.aligned.m8n8.x4.shared.b16 {%0,%1,%2,%3}, [%4];"
                 : "=r"(r[0]), "=r"(r[1]), "=r"(r[2]), "=r"(r[3]) : "r"(addr));
}
DINLINE void mma16816(float4& c, const uint32_t* a, uint32_t b0, uint32_t b1) {
    asm volatile(
        "mma.sync.aligned.m16n8k16.row.col.f32.f16.f16.f32 "
        "{%0,%1,%2,%3}, {%4,%5,%6,%7}, {%8,%9}, {%0,%1,%2,%3};"
        : "+f"(c.x), "+f"(c.y), "+f"(c.z), "+f"(c.w)
        : "r"(a[0]), "r"(a[1]), "r"(a[2]), "r"(a[3]), "r"(b0), "r"(b1));
}
DINLINE float ex2f(float x) {
    float e;
    asm("ex2.approx.f32 %0, %1;" : "=f"(e) : "f"(x));
    return e;
}

// ============ SMEM layout ============
static constexpr int ROW_BYTES  = 528;               // 256 fp16 + 16B pad
static constexpr int TILE_BYTES = 128 * ROW_BYTES;   // 67584
static constexpr int SMEM_DSUM  = 0;
static constexpr int SMEM_CPART = 512;
static constexpr int SMEM_A     = 4096;
static constexpr int SMEM_B0    = SMEM_A + TILE_BYTES;
static constexpr int SMEM_B1    = SMEM_B0 + TILE_BYTES;
static constexpr int SMEM_TOTAL = SMEM_B1 + TILE_BYTES;   // 206848

DINLINE void load_tile(uint32_t smem_dst, const __half* gsrc, int tid) {
#pragma unroll
    for (int i = 0; i < 16; ++i) {
        int u = tid + i * 256;
        int r = u >> 5, c = u & 31;
        uint32_t saddr = smem_dst + (uint32_t)r * ROW_BYTES + (uint32_t)c * 16;
        const char* g = (const char*)gsrc + (size_t)u * 16;
        asm volatile("cp.async.cg.shared.global [%0], [%1], 16;" :: "r"(saddr), "l"(g));
    }
}

// ============ kernel 1: normalize — 4 rows per warp, loads front-batched (MLP=8) ============
__global__ void __launch_bounds__(256) k_normalize(const float* __restrict__ q,
                                                   const float* __restrict__ p,
                                                   float* __restrict__ out) {
    const int wid  = threadIdx.x >> 5;
    const int lane = threadIdx.x & 31;
    const int row0 = blockIdx.x * 32 + wid * 4;      // 4 rows per warp, grid 256
    if (threadIdx.x < 32) g_denom[blockIdx.x * 32 + threadIdx.x] = 0.0f;
    if (blockIdx.x == 0 && threadIdx.x == 0) out[0] = 0.0f;

    float4 v[4][2];
#pragma unroll
    for (int rr = 0; rr < 4; ++rr) {
        const int row = row0 + rr;
        const float* src = (row < B_ROWS) ? q + (size_t)row * D_DIM
                                          : p + (size_t)(row - B_ROWS) * D_DIM;
        v[rr][0] = ((const float4*)src)[lane * 2];
        v[rr][1] = ((const float4*)src)[lane * 2 + 1];
    }

    float ss[4];
#pragma unroll
    for (int rr = 0; rr < 4; ++rr)
        ss[rr] = v[rr][0].x * v[rr][0].x + v[rr][0].y * v[rr][0].y
               + v[rr][0].z * v[rr][0].z + v[rr][0].w * v[rr][0].w
               + v[rr][1].x * v[rr][1].x + v[rr][1].y * v[rr][1].y
               + v[rr][1].z * v[rr][1].z + v[rr][1].w * v[rr][1].w;
#pragma unroll
    for (int o = 16; o; o >>= 1) {
#pragma unroll
        for (int rr = 0; rr < 4; ++rr)
            ss[rr] += __shfl_xor_sync(0xffffffffu, ss[rr], o);
    }
#pragma unroll
    for (int rr = 0; rr < 4; ++rr) {
        float inv = 1.0f / fmaxf(sqrtf(ss[rr]), 1e-12f);
        __half2 h[4];
        h[0] = __floats2half2_rn(v[rr][0].x * inv, v[rr][0].y * inv);
        h[1] = __floats2half2_rn(v[rr][0].z * inv, v[rr][0].w * inv);
        h[2] = __floats2half2_rn(v[rr][1].x * inv, v[rr][1].y * inv);
        h[3] = __floats2half2_rn(v[rr][1].z * inv, v[rr][1].w * inv);
        ((uint4*)(g_Z + (size_t)(row0 + rr) * D_DIM))[lane] = *(const uint4*)h;
    }
}

// ============ kernel 2: balanced upper-triangle Gram, A strip register-resident ============
// 148 CTAs, 256 threads = 8 warps as 4(M) x 2(N); warp tile 32x64.
__global__ void __launch_bounds__(256, 1) k_gemm_denom() {
    extern __shared__ __align__(1024) char smem[];
    const int tid    = threadIdx.x;
    const int wid    = tid >> 5;
    const int lane   = tid & 31;
    const int warp_m = wid & 3;
    const int warp_n = wid >> 2;
    uint32_t sbase = smem_u32(smem);
    float* dsum  = (float*)(smem + SMEM_DSUM);
    float* cpart = (float*)(smem + SMEM_CPART);

    const uint32_t lrow  = (uint32_t)(lane & 15) * ROW_BYTES + (uint32_t)(lane >> 4) * 16;
    const uint32_t abase = sbase + SMEM_A + (uint32_t)(warp_m * 32) * ROW_BYTES + lrow;
    const uint32_t boff  = (uint32_t)(warp_n * 64) * ROW_BYTES + lrow;

    const int t0 = (int)((unsigned)blockIdx.x * NTRI / NCTA);
    const int t1 = (int)(((unsigned)blockIdx.x + 1) * NTRI / NCTA);

    int t = t0;
#pragma unroll 1
    while (t < t1) {
        const int P = t / 65;
        const int r = t - P * 65;
        int it, jt0, runend;
        if (r < 64 - P) { it = P;      jt0 = P + r;                   runend = t + (64 - P - r); }
        else            { it = 63 - P; jt0 = (63 - P) + r - (64 - P); runend = t + (65 - r); }
        const int n = min(t1, runend) - t;

        load_tile(sbase + SMEM_A,  g_Z + (size_t)it * TILE * D_DIM, tid);
        load_tile(sbase + SMEM_B0, g_Z + (size_t)jt0 * TILE * D_DIM, tid);
        asm volatile("cp.async.commit_group;" ::: "memory");
        asm volatile("cp.async.wait_group 0;" ::: "memory");
        __syncthreads();

        // hoist A fragments for the whole strip into registers
        uint32_t areg[16][8];
#pragma unroll
        for (int ks = 0; ks < 16; ++ks) {
            ldsm_x4(abase + (uint32_t)ks * 32, areg[ks]);
            ldsm_x4(abase + 16u * ROW_BYTES + (uint32_t)ks * 32, areg[ks] + 4);
        }

        float rsum[2][2] = {{0.f, 0.f}, {0.f, 0.f}};

#pragma unroll 1
        for (int idx = 0; idx < n; ++idx) {
            const int jt = jt0 + idx;
            if (idx + 1 < n) {
                load_tile(sbase + ((idx + 1) & 1 ? SMEM_B1 : SMEM_B0),
                          g_Z + (size_t)(jt + 1) * TILE * D_DIM, tid);
                asm volatile("cp.async.commit_group;" ::: "memory");
                asm volatile("cp.async.wait_group 1;" ::: "memory");
            } else {
                asm volatile("cp.async.wait_group 0;" ::: "memory");
            }
            __syncthreads();

            const uint32_t bbase = sbase + ((idx & 1) ? SMEM_B1 : SMEM_B0) + boff;

            float4 acc[2][8];
#pragma unroll
            for (int mi = 0; mi < 2; ++mi)
#pragma unroll
                for (int nt = 0; nt < 8; ++nt) acc[mi][nt] = make_float4(0.f, 0.f, 0.f, 0.f);

#pragma unroll
            for (int ks = 0; ks < 16; ++ks) {
                uint32_t bf[4][4];
#pragma unroll
                for (int bt = 0; bt < 4; ++bt)
                    ldsm_x4(bbase + (uint32_t)(bt * 16) * ROW_BYTES + (uint32_t)ks * 32, bf[bt]);
#pragma unroll
                for (int bt = 0; bt < 4; ++bt) {
                    mma16816(acc[0][2 * bt],     areg[ks],     bf[bt][0], bf[bt][2]);
                    mma16816(acc[0][2 * bt + 1], areg[ks],     bf[bt][1], bf[bt][3]);
                    mma16816(acc[1][2 * bt],     areg[ks] + 4, bf[bt][0], bf[bt][2]);
                    mma16816(acc[1][2 * bt + 1], areg[ks] + 4, bf[bt][1], bf[bt][3]);
                }
            }
            __syncthreads();

            const bool offdiag = (jt != it);
            float colacc[16];
#pragma unroll
            for (int i = 0; i < 16; ++i) colacc[i] = 0.f;
#pragma unroll
            for (int mi = 0; mi < 2; ++mi) {
                float s0 = 0.f, s1 = 0.f;
#pragma unroll
                for (int nt = 0; nt < 8; ++nt) {
                    float4 c = acc[mi][nt];
                    float ex = ex2f(c.x * EXP_K), ey = ex2f(c.y * EXP_K);
                    float ez = ex2f(c.z * EXP_K), ew = ex2f(c.w * EXP_K);
                    s0 += ex + ey;
                    s1 += ez + ew;
                    colacc[nt * 2]     += ex + ez;
                    colacc[nt * 2 + 1] += ey + ew;
                }
                rsum[mi][0] += s0;
                rsum[mi][1] += s1;
            }
            if (offdiag) {
#pragma unroll
                for (int i = 0; i < 16; ++i) {
                    float v = colacc[i];
                    v += __shfl_xor_sync(0xffffffffu, v, 4);
                    v += __shfl_xor_sync(0xffffffffu, v, 8);
                    v += __shfl_xor_sync(0xffffffffu, v, 16);
                    colacc[i] = v;
                }
                if (lane < 4) {
#pragma unroll
                    for (int nt = 0; nt < 8; ++nt) {
                        cpart[warp_m * 128 + warp_n * 64 + nt * 8 + 2 * lane]     = colacc[nt * 2];
                        cpart[warp_m * 128 + warp_n * 64 + nt * 8 + 2 * lane + 1] = colacc[nt * 2 + 1];
                    }
                }
                __syncthreads();
                if (tid < 128) {
                    float v = cpart[tid] + cpart[128 + tid] + cpart[256 + tid] + cpart[384 + tid];
                    atomicAdd(&g_denom[jt * TILE + tid], v);
                }
            }
        }

        // strip row-sum contribution
#pragma unroll
        for (int mi = 0; mi < 2; ++mi)
#pragma unroll
            for (int h = 0; h < 2; ++h) {
                float v = rsum[mi][h];
                v += __shfl_xor_sync(0xffffffffu, v, 1);
                v += __shfl_xor_sync(0xffffffffu, v, 2);
                rsum[mi][h] = v;
            }
        __syncthreads();
        if ((lane & 3) == 0 && warp_n == 0) {
#pragma unroll
            for (int mi = 0; mi < 2; ++mi)
#pragma unroll
                for (int h = 0; h < 2; ++h)
                    dsum[warp_m * 32 + mi * 16 + h * 8 + (lane >> 2)] = rsum[mi][h];
        }
        __syncthreads();
        if ((lane & 3) == 0 && warp_n == 1) {
#pragma unroll
            for (int mi = 0; mi < 2; ++mi)
#pragma unroll
                for (int h = 0; h < 2; ++h) {
                    int rl = warp_m * 32 + mi * 16 + h * 8 + (lane >> 2);
                    atomicAdd(&g_denom[it * TILE + rl], dsum[rl] + rsum[mi][h]);
                }
        }
        __syncthreads();

        t += n;
    }
}

// ============ kernel 3: one pair per warp; positives + self-term removal + final sum ============
__global__ void __launch_bounds__(256) k_loss_partial(float* __restrict__ out) {
    const int wid  = threadIdx.x >> 5;
    const int lane = threadIdx.x & 31;
    const int i    = blockIdx.x * 8 + wid;         // pair 0..4095 (grid 512)

    uint4 a = ((const uint4*)(g_Z + (size_t)i * D_DIM))[lane];
    uint4 b = ((const uint4*)(g_Z + (size_t)(i + B_ROWS) * D_DIM))[lane];
    const __half2* pa = (const __half2*)&a;
    const __half2* pb = (const __half2*)&b;
    float d = 0.f, saa = 0.f, sbb = 0.f;
#pragma unroll
    for (int j = 0; j < 4; ++j) {
        float2 fa = __half22float2(pa[j]);
        float2 fb = __half22float2(pb[j]);
        d   += fa.x * fb.x + fa.y * fb.y;
        saa += fa.x * fa.x + fa.y * fa.y;
        sbb += fb.x * fb.x + fb.y * fb.y;
    }
#pragma unroll
    for (int o = 16; o; o >>= 1) {
        d   += __shfl_xor_sync(0xffffffffu, d, o);
        saa += __shfl_xor_sync(0xffffffffu, saa, o);
        sbb += __shfl_xor_sync(0xffffffffu, sbb, o);
    }
    __shared__ float sacc[8];
    if (lane == 0) {
        float di = g_denom[i]          - exp2f(saa * EXP_K);
        float dj = g_denom[i + B_ROWS] - exp2f(sbb * EXP_K);
        sacc[wid] = -4.0f * d + logf(di) + logf(dj);
    }
    __syncthreads();
    if (threadIdx.x == 0) {
        float s = 0.0f;
#pragma unroll
        for (int w = 0; w < 8; ++w) s += sacc[w];
        atomicAdd(out, s * (1.0f / (float)N_TOT));
    }
}

// ============ launch ============
extern "C" void kernel_launch(void* const* d_in, const int* in_sizes, int n_in,
                              void* d_out, int out_size) {
    const float* q = (const float*)d_in[0];
    const float* p = (const float*)d_in[1];
    (void)in_sizes; (void)n_in; (void)out_size;

    static bool attr_set = false;
    if (!attr_set) {
        cudaFuncSetAttribute(k_gemm_denom, cudaFuncAttributeMaxDynamicSharedMemorySize, SMEM_TOTAL);
        attr_set = true;
    }

    k_normalize<<<N_TOT / 32, 256>>>(q, p, (float*)d_out);
    k_gemm_denom<<<NCTA, 256, SMEM_TOTAL>>>();
    k_loss_partial<<<512, 256>>>((float*)d_out);
}